// round 9
// baseline (speedup 1.0000x reference)
#include <cuda_runtime.h>
#include <cstdint>

#define BATCH 32
#define SEQ   512
#define DIMK  64
#define DPITCH 1024
#define BIGF  1e30f
#define L2E   1.4426950408889634f
#define LN2   0.6931471805599453f

#define NWORKER 116      // GEMM worker CTAs (total grid = 32 + 116 = 148)
#define NLEVEL  28       // anti-diagonal levels of 32 diagonals (L = (i0+j0)/32)
#define NTILE   2048     // 32 batches * 4 i-tiles * 16 j-tiles

// Diagonal-major distance scratch: Ddiag[b][p][i] = D[b, i, p-i]
__device__ float g_Ddiag[BATCH * DPITCH * SEQ];
// per-(batch, level) tile completion counters
__device__ int g_cnt[BATCH * NLEVEL];

__global__ void zero_cnt_kernel() {
  int t = threadIdx.x;
  if (t < BATCH * NLEVEL) g_cnt[t] = 0;
}

// tiles per batch at level L (i0 in {0,128,256,384}, j0 in {0,32,...,480})
__device__ __forceinline__ int cL(int L) {
  int vimax = L >> 2; if (vimax > 3) vimax = 3;
  int vimin = (L - 12) >> 2; if (vimin < 0) vimin = 0;
  return vimax - vimin + 1;
}

__device__ __forceinline__ int ld_acq(const int* p) {
  int v;
  asm volatile("ld.acquire.gpu.global.b32 %0, [%1];" : "=r"(v) : "l"(p) : "memory");
  return v;
}

__device__ __forceinline__ float ex2f(float x) {
  float r; asm("ex2.approx.f32 %0, %1;" : "=f"(r) : "f"(x)); return r;
}
__device__ __forceinline__ float lg2f(float x) {
  float r; asm("lg2.approx.f32 %0, %1;" : "=f"(r) : "f"(x)); return r;
}
__device__ __forceinline__ float softmin3s(float a, float b, float c) {
  float u = fminf(a, b), v = fmaxf(a, b);
  float mn = fminf(u, c);
  float mx = fmaxf(v, c);
  float md = fmaxf(u, fminf(v, c));
  float s = 1.0f + ex2f(mn - md) + ex2f(mn - mx);
  return mn - lg2f(s);
}

#define YS_STRIDE 36
#define DST_STRIDE 33

// ---------------------------------------------------------------------------
// GEMM worker role: persistent CTA, grabs 128(i) x 32(j) tiles in priority
// order (level-major, batch round-robin), writes diag-major with <=128B runs,
// then releases the per-(batch,level) counter.
// ---------------------------------------------------------------------------
__device__ void gemm_worker(const float* __restrict__ X,
                            const float* __restrict__ Y, int wq) {
  __shared__ float Ys[DIMK * YS_STRIDE];   // [k][j], 32 wide
  __shared__ float y2s[32];
  __shared__ float Dst[128 * DST_STRIDE];

  const int t = threadIdx.x;
  const int w = t >> 5, lane = t & 31;

  for (int q = wq; q < NTILE; q += NWORKER) {
    // decode priority index q -> (L, k, b) -> (b, i0, j0)
    int qq = q, L = 0;
    for (;;) {
      int blk = 32 * cL(L);
      if (qq < blk) break;
      qq -= blk; L++;
    }
    int k_in = qq >> 5;
    int b = qq & 31;
    int vimin = (L - 12) >> 2; if (vimin < 0) vimin = 0;
    int vi = vimin + k_in;
    int i0 = vi << 7;
    int j0 = (L - (vi << 2)) << 5;

    const float* Xb = X + ((size_t)b * SEQ + i0) * DIMK;
    const float* Yb = Y + ((size_t)b * SEQ + j0) * DIMK;

    // Y tile transposed into smem
    for (int e = t; e < 32 * DIMK; e += 128) {
      int j = e >> 6;
      int kk = e & 63;
      Ys[kk * YS_STRIDE + j] = Yb[e];
    }

    // X row -> regs
    float xr[DIMK];
    float x2 = 0.f;
#pragma unroll
    for (int k4 = 0; k4 < DIMK; k4 += 4) {
      float4 v = *reinterpret_cast<const float4*>(Xb + (size_t)t * DIMK + k4);
      xr[k4] = v.x; xr[k4 + 1] = v.y; xr[k4 + 2] = v.z; xr[k4 + 3] = v.w;
    }
#pragma unroll
    for (int kk = 0; kk < DIMK; kk++) x2 += xr[kk] * xr[kk];

    __syncthreads();

    if (t < 32) {
      float a = 0.f;
#pragma unroll
      for (int kk = 0; kk < DIMK; kk++) {
        float yv = Ys[kk * YS_STRIDE + t];
        a += yv * yv;
      }
      y2s[t] = a;
    }
    __syncthreads();

    // 4 chunks of 8 columns into Dst (own row, no sync needed between chunks)
    for (int jb = 0; jb < 4; jb++) {
      float acc[8];
#pragma unroll
      for (int m = 0; m < 8; m++) acc[m] = 0.f;
#pragma unroll
      for (int kk = 0; kk < DIMK; kk++) {
        const float4 ya = *reinterpret_cast<const float4*>(&Ys[kk * YS_STRIDE + jb * 8]);
        const float4 yb = *reinterpret_cast<const float4*>(&Ys[kk * YS_STRIDE + jb * 8 + 4]);
        const float xv = xr[kk];
        acc[0] += xv * ya.x; acc[1] += xv * ya.y;
        acc[2] += xv * ya.z; acc[3] += xv * ya.w;
        acc[4] += xv * yb.x; acc[5] += xv * yb.y;
        acc[6] += xv * yb.z; acc[7] += xv * yb.w;
      }
#pragma unroll
      for (int m = 0; m < 8; m++) {
        Dst[t * DST_STRIDE + jb * 8 + m] = x2 + y2s[jb * 8 + m] - 2.f * acc[m];
      }
    }
    __syncthreads();

    // diag-major store: tile diag d = i + j in [0, 158], runs up to 32 long
    float* gout = g_Ddiag + (size_t)b * (DPITCH * SEQ);
    const int p0 = i0 + j0;
    for (int d = w; d < 128 + 32 - 1; d += 4) {
      int lo = d - 31 > 0 ? d - 31 : 0;
      int hi = d < 127 ? d : 127;
      int i = lo + lane;
      if (i <= hi) {
        gout[(size_t)(p0 + d) * SEQ + (i0 + i)] =
            Dst[i * DST_STRIDE + (d - i)];
      }
    }
    __syncthreads();

    if (t == 0) {
      __threadfence();
      atomicAdd(&g_cnt[b * NLEVEL + L], 1);
    }
  }
}

// ---------------------------------------------------------------------------
// DP role: R2 wavefront DP (4 warps, 4 rows/thread, barrier per step),
// with level waits inserted at prefetch boundaries.
// ---------------------------------------------------------------------------
__device__ void dp_role(float* __restrict__ out, int b) {
  const int t = threadIdx.x;
  const int lane = t & 31, w = t >> 5;

  __shared__ float sb1[2][4];
  __shared__ float sb2[2][4];
  if (t < 8) {
    (&sb1[0][0])[t] = BIGF;
    (&sb2[0][0])[t] = BIGF;
  }

  float v1[4], v2[4];
#pragma unroll
  for (int k = 0; k < 4; k++) { v1[k] = BIGF; v2[k] = BIGF; }

  const float* base = g_Ddiag + (size_t)b * (DPITCH * SEQ) + 4 * t;
  const int* cnt = &g_cnt[b * NLEVEL];
  int Ldone = -1;
  __syncthreads();

#define DP_WAIT(LNEED)                                                        \
  {                                                                           \
    int Ln = (LNEED);                                                         \
    if (Ln > 27) Ln = 27;                                                     \
    if (Ln > Ldone) {                                                         \
      if (t == 0) {                                                           \
        for (int L_ = Ldone + 1; L_ <= Ln; ++L_) {                            \
          int tgt = cL(L_);                                                   \
          while (ld_acq(cnt + L_) < tgt) __nanosleep(64);                     \
        }                                                                     \
        __threadfence();                                                      \
      }                                                                       \
      __syncthreads();                                                        \
      Ldone = Ln;                                                             \
    }                                                                         \
  }

#define DP_STEP(P, G4)                                                        \
  {                                                                           \
    const int rs = (P) & 1;                                                   \
    float nb1 = __shfl_up_sync(0xffffffffu, v1[3], 1);                        \
    float nb2 = __shfl_up_sync(0xffffffffu, v2[3], 1);                        \
    if (lane == 0) {                                                          \
      nb1 = (w == 0) ? BIGF : sb1[rs][w - 1];                                 \
      nb2 = (w == 0) ? (((P) == 0) ? 0.0f : BIGF) : sb2[rs][w - 1];           \
    }                                                                         \
    float sm0 = softmin3s(nb2,   nb1,   v1[0]);                               \
    float sm1 = softmin3s(v2[0], v1[0], v1[1]);                               \
    float sm2 = softmin3s(v2[1], v1[1], v1[2]);                               \
    float sm3 = softmin3s(v2[2], v1[2], v1[3]);                               \
    unsigned pr = (unsigned)((P) - 4 * t);                                    \
    float n0 = (pr      < (unsigned)SEQ) ? fmaf((G4).x, L2E, sm0) : BIGF;     \
    float n1 = (pr - 1u < (unsigned)SEQ) ? fmaf((G4).y, L2E, sm1) : BIGF;     \
    float n2 = (pr - 2u < (unsigned)SEQ) ? fmaf((G4).z, L2E, sm2) : BIGF;     \
    float n3 = (pr - 3u < (unsigned)SEQ) ? fmaf((G4).w, L2E, sm3) : BIGF;     \
    v2[0] = v1[0]; v2[1] = v1[1]; v2[2] = v1[2]; v2[3] = v1[3];               \
    v1[0] = n0; v1[1] = n1; v1[2] = n2; v1[3] = n3;                           \
    if (lane == 31) { sb1[rs ^ 1][w] = v1[3]; sb2[rs ^ 1][w] = v2[3]; }       \
    __syncthreads();                                                          \
  }

#define LOADD(G, DST)                                                         \
  {                                                                           \
    _Pragma("unroll") for (int j_ = 0; j_ < 8; j_++) {                        \
      int p_ = 8 * (G) + j_; if (p_ > 1022) p_ = 1022;                        \
      (DST)[j_] = *reinterpret_cast<const float4*>(base + (size_t)p_ * SEQ);  \
    }                                                                         \
  }

  float4 cur[8];
  DP_WAIT(0);
  LOADD(0, cur);

  for (int g = 0; g < 127; ++g) {
    DP_WAIT((8 * g + 15) >> 5);
    float4 nxt[8];
    LOADD(g + 1, nxt);
#pragma unroll
    for (int j = 0; j < 8; j++) {
      const int p = 8 * g + j;
      DP_STEP(p, cur[j]);
    }
#pragma unroll
    for (int j = 0; j < 8; j++) cur[j] = nxt[j];
  }
  // epilogue: p = 1016 .. 1022
#pragma unroll
  for (int j = 0; j < 7; j++) {
    const int p = 1016 + j;
    DP_STEP(p, cur[j]);
  }

  if (t == 127) out[b] = v1[3] * LN2;   // R(511,511), back to nat domain
#undef DP_STEP
#undef LOADD
#undef DP_WAIT
}

// ---------------------------------------------------------------------------
__global__ __launch_bounds__(128) void fused_kernel(
    const float* __restrict__ X, const float* __restrict__ Y,
    float* __restrict__ out) {
  if (blockIdx.x < BATCH) {
    dp_role(out, blockIdx.x);
  } else {
    gemm_worker(X, Y, blockIdx.x - BATCH);
  }
}

// ---------------------------------------------------------------------------
extern "C" void kernel_launch(void* const* d_in, const int* in_sizes, int n_in,
                              void* d_out, int out_size) {
  const float* X = (const float*)d_in[0];
  const float* Y = (const float*)d_in[1];
  float* out = (float*)d_out;

  zero_cnt_kernel<<<1, BATCH * NLEVEL>>>();
  fused_kernel<<<BATCH + NWORKER, 128>>>(X, Y, out);
}

// round 10
// speedup vs baseline: 1.0730x; 1.0730x over previous
#include <cuda_runtime.h>
#include <cstdint>

#define BATCH 32
#define SEQ   512
#define DIMK  64
#define DPITCH 1024
#define BIGF  1e30f
#define L2E   1.4426950408889634f
#define LN2   0.6931471805599453f

// Diagonal-major distance scratch: Ddiag[b][p][i] = D[b, i, p-i]  (64 MB)
__device__ float g_Ddiag[BATCH * DPITCH * SEQ];

__device__ __forceinline__ float ex2f(float x) {
  float r; asm("ex2.approx.f32 %0, %1;" : "=f"(r) : "f"(x)); return r;
}
__device__ __forceinline__ float lg2f(float x) {
  float r; asm("lg2.approx.f32 %0, %1;" : "=f"(r) : "f"(x)); return r;
}
// softmin (base-2 domain): exact min/median/max; 2 EX2 + 1 LG2.
__device__ __forceinline__ float softmin3s(float a, float b, float c) {
  float u = fminf(a, b), v = fmaxf(a, b);
  float mn = fminf(u, c);
  float mx = fmaxf(v, c);
  float md = fmaxf(u, fminf(v, c));
  float s = 1.0f + ex2f(mn - md) + ex2f(mn - mx);
  return mn - lg2f(s);
}

// ---------------------------------------------------------------------------
// Phase 1: D = x2 + y2 - 2 x.y, diagonal-major output.
// One CTA (128 threads) per 128(i) x 32(j) tile; grid (4, 16, 32).
// Diag-major stores are runs of up to 32 consecutive i (128B transactions),
// staged via Dst[128][33] (stride 33 == 1 mod 32 -> conflict-free).
// (This is the R9 worker body, proven correct, queue stripped.)
// ---------------------------------------------------------------------------
#define YS_STRIDE 36
#define DST_STRIDE 33

__global__ __launch_bounds__(128) void gemm_diag_kernel(
    const float* __restrict__ X, const float* __restrict__ Y) {
  __shared__ float Ys[DIMK * YS_STRIDE];   // [k][j], 32 wide
  __shared__ float y2s[32];
  __shared__ float Dst[128 * DST_STRIDE];

  const int t = threadIdx.x;
  const int w = t >> 5, lane = t & 31;
  const int i0 = blockIdx.x << 7;   // 0..3  -> 0,128,256,384
  const int j0 = blockIdx.y << 5;   // 0..15 -> 0,32,...,480
  const int b  = blockIdx.z;

  const float* Xb = X + ((size_t)b * SEQ + i0) * DIMK;
  const float* Yb = Y + ((size_t)b * SEQ + j0) * DIMK;

  // Y tile transposed into smem
  for (int e = t; e < 32 * DIMK; e += 128) {
    int j = e >> 6;
    int kk = e & 63;
    Ys[kk * YS_STRIDE + j] = Yb[e];
  }

  // X row -> regs
  float xr[DIMK];
  float x2 = 0.f;
#pragma unroll
  for (int k4 = 0; k4 < DIMK; k4 += 4) {
    float4 v = *reinterpret_cast<const float4*>(Xb + (size_t)t * DIMK + k4);
    xr[k4] = v.x; xr[k4 + 1] = v.y; xr[k4 + 2] = v.z; xr[k4 + 3] = v.w;
  }
#pragma unroll
  for (int kk = 0; kk < DIMK; kk++) x2 += xr[kk] * xr[kk];

  __syncthreads();

  if (t < 32) {
    float a = 0.f;
#pragma unroll
    for (int kk = 0; kk < DIMK; kk++) {
      float yv = Ys[kk * YS_STRIDE + t];
      a += yv * yv;
    }
    y2s[t] = a;
  }
  __syncthreads();

  // 4 chunks of 8 columns into Dst (each thread writes only its own row)
  for (int jb = 0; jb < 4; jb++) {
    float acc[8];
#pragma unroll
    for (int m = 0; m < 8; m++) acc[m] = 0.f;
#pragma unroll
    for (int kk = 0; kk < DIMK; kk++) {
      const float4 ya = *reinterpret_cast<const float4*>(&Ys[kk * YS_STRIDE + jb * 8]);
      const float4 yb = *reinterpret_cast<const float4*>(&Ys[kk * YS_STRIDE + jb * 8 + 4]);
      const float xv = xr[kk];
      acc[0] += xv * ya.x; acc[1] += xv * ya.y;
      acc[2] += xv * ya.z; acc[3] += xv * ya.w;
      acc[4] += xv * yb.x; acc[5] += xv * yb.y;
      acc[6] += xv * yb.z; acc[7] += xv * yb.w;
    }
#pragma unroll
    for (int m = 0; m < 8; m++) {
      Dst[t * DST_STRIDE + jb * 8 + m] = x2 + y2s[jb * 8 + m] - 2.f * acc[m];
    }
  }
  __syncthreads();

  // diag-major store: tile diag d = i + j in [0, 158], runs up to 32 long
  float* gout = g_Ddiag + (size_t)b * (DPITCH * SEQ);
  const int p0 = i0 + j0;
  for (int d = w; d < 128 + 32 - 1; d += 4) {
    int lo = d - 31 > 0 ? d - 31 : 0;
    int hi = d < 127 ? d : 127;
    int i = lo + lane;
    if (i <= hi) {
      gout[(size_t)(p0 + d) * SEQ + (i0 + i)] =
          Dst[i * DST_STRIDE + (d - i)];
    }
  }
}

// ---------------------------------------------------------------------------
// Phase 2: wavefront DP — R2 verbatim (measured 135.9us, regs=93).
// 4 warps, 4 consecutive rows per thread; parity-double-buffered smem
// mailboxes; one barrier per step; 8-deep float4 register prefetch.
// Base-2 scaled domain (R' = R * log2e).
// ---------------------------------------------------------------------------
__global__ __launch_bounds__(128) void softdtw_dp_kernel(float* __restrict__ out) {
  const int b = blockIdx.x;
  const int t = threadIdx.x;
  const int lane = t & 31, w = t >> 5;

  __shared__ float sb1[2][4];
  __shared__ float sb2[2][4];
  if (t < 8) {
    (&sb1[0][0])[t] = BIGF;
    (&sb2[0][0])[t] = BIGF;
  }

  float v1[4], v2[4];
#pragma unroll
  for (int k = 0; k < 4; k++) { v1[k] = BIGF; v2[k] = BIGF; }

  const float* base = g_Ddiag + (size_t)b * (DPITCH * SEQ) + 4 * t;
  __syncthreads();

#define DP_STEP(P, G4)                                                        \
  {                                                                           \
    const int rs = (P) & 1;                                                   \
    float nb1 = __shfl_up_sync(0xffffffffu, v1[3], 1);                        \
    float nb2 = __shfl_up_sync(0xffffffffu, v2[3], 1);                        \
    if (lane == 0) {                                                          \
      nb1 = (w == 0) ? BIGF : sb1[rs][w - 1];                                 \
      nb2 = (w == 0) ? (((P) == 0) ? 0.0f : BIGF) : sb2[rs][w - 1];           \
    }                                                                         \
    float sm0 = softmin3s(nb2,   nb1,   v1[0]);                               \
    float sm1 = softmin3s(v2[0], v1[0], v1[1]);                               \
    float sm2 = softmin3s(v2[1], v1[1], v1[2]);                               \
    float sm3 = softmin3s(v2[2], v1[2], v1[3]);                               \
    unsigned pr = (unsigned)((P) - 4 * t);                                    \
    float n0 = (pr      < (unsigned)SEQ) ? fmaf((G4).x, L2E, sm0) : BIGF;     \
    float n1 = (pr - 1u < (unsigned)SEQ) ? fmaf((G4).y, L2E, sm1) : BIGF;     \
    float n2 = (pr - 2u < (unsigned)SEQ) ? fmaf((G4).z, L2E, sm2) : BIGF;     \
    float n3 = (pr - 3u < (unsigned)SEQ) ? fmaf((G4).w, L2E, sm3) : BIGF;     \
    v2[0] = v1[0]; v2[1] = v1[1]; v2[2] = v1[2]; v2[3] = v1[3];               \
    v1[0] = n0;    v1[1] = n1;    v1[2] = n2;    v1[3] = n3;                  \
    if (lane == 31) { sb1[rs ^ 1][w] = v1[3]; sb2[rs ^ 1][w] = v2[3]; }       \
    __syncthreads();                                                          \
  }

  // prefetch pipeline: groups of 8 diagonals
  float4 cur[8];
#pragma unroll
  for (int j = 0; j < 8; j++)
    cur[j] = *reinterpret_cast<const float4*>(base + (size_t)j * SEQ);

  for (int g = 0; g < 127; ++g) {
    float4 nxt[8];
#pragma unroll
    for (int j = 0; j < 8; j++)
      nxt[j] = *reinterpret_cast<const float4*>(base + (size_t)(8 * (g + 1) + j) * SEQ);
#pragma unroll
    for (int j = 0; j < 8; j++) {
      const int p = 8 * g + j;
      DP_STEP(p, cur[j]);
    }
#pragma unroll
    for (int j = 0; j < 8; j++) cur[j] = nxt[j];
  }
  // epilogue: p = 1016 .. 1022
#pragma unroll
  for (int j = 0; j < 7; j++) {
    const int p = 1016 + j;
    DP_STEP(p, cur[j]);
  }

  if (t == 127) out[b] = v1[3] * LN2;  // R(511,511), back to nat domain
#undef DP_STEP
}

// ---------------------------------------------------------------------------
extern "C" void kernel_launch(void* const* d_in, const int* in_sizes, int n_in,
                              void* d_out, int out_size) {
  const float* X = (const float*)d_in[0];
  const float* Y = (const float*)d_in[1];
  float* out = (float*)d_out;

  dim3 grid_g(4, 16, BATCH);     // 2048 tiles of 128(i) x 32(j)
  gemm_diag_kernel<<<grid_g, 128>>>(X, Y);
  softdtw_dp_kernel<<<BATCH, 128>>>(out);
}